// round 8
// baseline (speedup 1.0000x reference)
#include <cuda_runtime.h>
#include <math.h>
#include <stdint.h>

// Problem dims (fixed by the reference)
#define TT  16384   // tokens = B*S
#define HH  1024    // hidden
#define EE  8       // routed experts
#define KK  2       // top-k
#define DEE 128     // routed expert hidden
#define DSS 512     // shared expert hidden

// ---------------- device scratch ----------------
__device__ int   g_cnt[EE];
__device__ int   g_off[EE + 1];
__device__ int   g_pos[EE];
__device__ int   g_top_idx[TT * KK];
__device__ float g_top_w[TT * KK];
__device__ int   g_tok[TT * KK];
__device__ float g_wt[TT * KK];
__device__ int   g_slot[TT * KK];
__device__ float g_h1[TT * KK * DEE];
__device__ float g_hs[TT * DSS];
__device__ float g_y2[(size_t)TT * KK * HH];

// ---------------- small kernels (unchanged from passing R1) ----------------
__global__ void k_zero_cnt() {
    if (threadIdx.x < EE) g_cnt[threadIdx.x] = 0;
}

__global__ void k_gate(const float* __restrict__ x, const float* __restrict__ Wg) {
    int warp = (blockIdx.x * blockDim.x + threadIdx.x) >> 5;
    int lane = threadIdx.x & 31;
    if (warp >= TT) return;
    const float* xr = x + (size_t)warp * HH;
    float acc[EE];
#pragma unroll
    for (int e = 0; e < EE; e++) acc[e] = 0.f;
    for (int j = lane; j < HH; j += 32) {
        float xv = xr[j];
#pragma unroll
        for (int e = 0; e < EE; e++) acc[e] += xv * Wg[e * HH + j];
    }
#pragma unroll
    for (int e = 0; e < EE; e++) {
#pragma unroll
        for (int off = 16; off; off >>= 1)
            acc[e] += __shfl_xor_sync(0xFFFFFFFFu, acc[e], off);
    }
    if (lane == 0) {
        float mx = acc[0];
#pragma unroll
        for (int e = 1; e < EE; e++) mx = fmaxf(mx, acc[e]);
        float p[EE], s = 0.f;
#pragma unroll
        for (int e = 0; e < EE; e++) { p[e] = expf(acc[e] - mx); s += p[e]; }
        int i0 = 0;
#pragma unroll
        for (int e = 1; e < EE; e++) if (p[e] > p[i0]) i0 = e;
        int i1 = (i0 == 0) ? 1 : 0;
#pragma unroll
        for (int e = 0; e < EE; e++) if (e != i0 && p[e] > p[i1]) i1 = e;
        float sc0 = p[i0] / s, sc1 = p[i1] / s;
        float inv = 1.f / (sc0 + sc1 + 1e-20f);
        g_top_idx[warp * 2 + 0] = i0;
        g_top_idx[warp * 2 + 1] = i1;
        g_top_w[warp * 2 + 0] = sc0 * inv;
        g_top_w[warp * 2 + 1] = sc1 * inv;
        atomicAdd(&g_cnt[i0], 1);
        atomicAdd(&g_cnt[i1], 1);
    }
}

__global__ void k_prefix() {
    if (threadIdx.x == 0) {
        int acc = 0;
#pragma unroll
        for (int e = 0; e < EE; e++) { g_off[e] = acc; acc += g_cnt[e]; }
        g_off[EE] = acc;
    }
    if (threadIdx.x < EE) g_pos[threadIdx.x] = 0;
}

__global__ void k_scatter() {
    int t = blockIdx.x * blockDim.x + threadIdx.x;
    if (t >= TT) return;
#pragma unroll
    for (int k = 0; k < KK; k++) {
        int e = g_top_idx[t * 2 + k];
        int s = g_off[e] + atomicAdd(&g_pos[e], 1);
        g_tok[s] = t;
        g_wt[s] = g_top_w[t * 2 + k];
        g_slot[t * 2 + k] = s;
    }
}

// ---------------- 3xTF32 mma GEMM: C[M,N] = A[M,K] * B[N,K]^T ----------------
#define BM 128
#define BN 128
#define BK 16
#define PAD 8
#define NTH 256

__device__ __forceinline__ uint32_t f2tf32(float f) {
    uint32_t r;
    asm("cvt.rna.tf32.f32 %0, %1;" : "=r"(r) : "f"(f));
    return r;
}

#define MMATF32(d, a, b) \
    asm volatile("mma.sync.aligned.m16n8k8.row.col.f32.tf32.tf32.f32 " \
                 "{%0,%1,%2,%3}, {%4,%5,%6,%7}, {%8,%9}, {%0,%1,%2,%3};" \
                 : "+f"((d)[0]), "+f"((d)[1]), "+f"((d)[2]), "+f"((d)[3]) \
                 : "r"((a)[0]), "r"((a)[1]), "r"((a)[2]), "r"((a)[3]), \
                   "r"((b)[0]), "r"((b)[1]))

template <bool GATHER, bool RELU, bool HASBIAS, bool SCALE>
__device__ __forceinline__ void gemm_tile(
    const float* __restrict__ A, int lda,
    const float* __restrict__ B, int ldb,
    const float* __restrict__ bias,
    float* __restrict__ C, int ldc,
    int Kd, int m0, int m_end, int n0,
    const int* __restrict__ gidx,
    const float* __restrict__ rowsc)
{
    __shared__ float As[BK][BM + PAD];
    __shared__ float Bs[BK][BN + PAD];
    const int tid  = threadIdx.x;
    const int lane = tid & 31;
    const int wid  = tid >> 5;
    const int wm   = wid & 1;    // m half (64 rows)
    const int wn   = wid >> 1;   // n quarter (32 cols)

    float acc[4][4][4];
#pragma unroll
    for (int i = 0; i < 4; i++)
#pragma unroll
        for (int j = 0; j < 4; j++)
#pragma unroll
            for (int q = 0; q < 4; q++) acc[i][j][q] = 0.f;

    // staging map identical to passing R1 kernel
    const float* aptr[2]; bool aval[2]; int arow[2], acol[2];
    const float* bptr[2]; int brow[2], bcol[2];
#pragma unroll
    for (int i = 0; i < 2; i++) {
        int li = tid * 2 + i;
        int r = li >> 2;
        int c = (li & 3) << 2;
        arow[i] = r; acol[i] = c;
        int gm = m0 + r;
        aval[i] = gm < m_end;
        int src = 0;
        if (aval[i]) src = GATHER ? gidx[gm] : gm;
        aptr[i] = A + (size_t)src * lda + c;
        brow[i] = r; bcol[i] = c;
        bptr[i] = B + (size_t)(n0 + r) * ldb + c;
    }

    for (int k0 = 0; k0 < Kd; k0 += BK) {
        __syncthreads();
#pragma unroll
        for (int i = 0; i < 2; i++) {
            float4 av = aval[i] ? *(const float4*)(aptr[i] + k0)
                                : make_float4(0.f, 0.f, 0.f, 0.f);
            As[acol[i] + 0][arow[i]] = av.x;
            As[acol[i] + 1][arow[i]] = av.y;
            As[acol[i] + 2][arow[i]] = av.z;
            As[acol[i] + 3][arow[i]] = av.w;
            float4 bv = *(const float4*)(bptr[i] + k0);
            Bs[bcol[i] + 0][brow[i]] = bv.x;
            Bs[bcol[i] + 1][brow[i]] = bv.y;
            Bs[bcol[i] + 2][brow[i]] = bv.z;
            Bs[bcol[i] + 3][brow[i]] = bv.w;
        }
        __syncthreads();

#pragma unroll
        for (int ks = 0; ks < 2; ks++) {
            const int kk = ks * 8 + (lane & 3);
            const int r0 = wm * 64 + (lane >> 2);
            uint32_t ah[4][4], al[4][4];
#pragma unroll
            for (int mi = 0; mi < 4; mi++) {
                float f0 = As[kk][r0 + mi * 16];
                float f1 = As[kk][r0 + mi * 16 + 8];
                float f2 = As[kk + 4][r0 + mi * 16];
                float f3 = As[kk + 4][r0 + mi * 16 + 8];
                ah[mi][0] = f2tf32(f0); al[mi][0] = f2tf32(f0 - __uint_as_float(ah[mi][0]));
                ah[mi][1] = f2tf32(f1); al[mi][1] = f2tf32(f1 - __uint_as_float(ah[mi][1]));
                ah[mi][2] = f2tf32(f2); al[mi][2] = f2tf32(f2 - __uint_as_float(ah[mi][2]));
                ah[mi][3] = f2tf32(f3); al[mi][3] = f2tf32(f3 - __uint_as_float(ah[mi][3]));
            }
            const int c0 = wn * 32 + (lane >> 2);
            uint32_t bh[4][2], bl[4][2];
#pragma unroll
            for (int nj = 0; nj < 4; nj++) {
                float f0 = Bs[kk][c0 + nj * 8];
                float f1 = Bs[kk + 4][c0 + nj * 8];
                bh[nj][0] = f2tf32(f0); bl[nj][0] = f2tf32(f0 - __uint_as_float(bh[nj][0]));
                bh[nj][1] = f2tf32(f1); bl[nj][1] = f2tf32(f1 - __uint_as_float(bh[nj][1]));
            }
#pragma unroll
            for (int mi = 0; mi < 4; mi++)
#pragma unroll
                for (int nj = 0; nj < 4; nj++) {
                    MMATF32(acc[mi][nj], ah[mi], bh[nj]);
                    MMATF32(acc[mi][nj], ah[mi], bl[nj]);
                    MMATF32(acc[mi][nj], al[mi], bh[nj]);
                }
        }
    }

    // ---- epilogue: (+bias) (*rowscale) (relu) -> C ----
#pragma unroll
    for (int mi = 0; mi < 4; mi++) {
#pragma unroll
        for (int half = 0; half < 2; half++) {
            int gm = m0 + wm * 64 + mi * 16 + (lane >> 2) + half * 8;
            if (gm >= m_end) continue;
            float sc = SCALE ? rowsc[gm] : 1.f;
#pragma unroll
            for (int nj = 0; nj < 4; nj++) {
                int col = n0 + wn * 32 + nj * 8 + (lane & 3) * 2;
                float v0 = acc[mi][nj][half * 2 + 0];
                float v1 = acc[mi][nj][half * 2 + 1];
                if (HASBIAS) { v0 += bias[col]; v1 += bias[col + 1]; }
                if (SCALE)   { v0 *= sc; v1 *= sc; }
                if (RELU)    { v0 = fmaxf(v0, 0.f); v1 = fmaxf(v1, 0.f); }
                *(float2*)(C + (size_t)gm * ldc + col) = make_float2(v0, v1);
            }
        }
    }
}

// ---------------- GEMM wrappers (same shapes/grids as passing R1) ----------------
__global__ __launch_bounds__(NTH) void k_shared_fc1(
    const float* __restrict__ x, const float* __restrict__ Ws1,
    const float* __restrict__ bs1)
{
    gemm_tile<false, true, true, false>(
        x, HH, Ws1, HH, bs1, g_hs, DSS, HH,
        blockIdx.x * BM, TT, blockIdx.y * BN, nullptr, nullptr);
}

__global__ __launch_bounds__(NTH) void k_shared_fc2(
    const float* __restrict__ Ws2, const float* __restrict__ bs2,
    float* __restrict__ out)
{
    gemm_tile<false, false, true, false>(
        g_hs, DSS, Ws2, DSS, bs2, out, HH, DSS,
        blockIdx.x * BM, TT, blockIdx.y * BN, nullptr, nullptr);
}

__global__ __launch_bounds__(NTH) void k_routed_fc1(
    const float* __restrict__ x, const float* __restrict__ W1,
    const float* __restrict__ b1)
{
    int e = blockIdx.z;
    int s0 = g_off[e], s1 = g_off[e + 1];
    int m0 = s0 + blockIdx.x * BM;
    if (m0 >= s1) return;
    gemm_tile<true, true, true, false>(
        x, HH, W1 + (size_t)e * DEE * HH, HH, b1 + e * DEE,
        g_h1, DEE, HH, m0, s1, 0, g_tok, nullptr);
}

__global__ __launch_bounds__(NTH) void k_routed_fc2(
    const float* __restrict__ W2, const float* __restrict__ b2)
{
    int e = blockIdx.z;
    int s0 = g_off[e], s1 = g_off[e + 1];
    int m0 = s0 + blockIdx.x * BM;
    if (m0 >= s1) return;
    gemm_tile<false, false, true, true>(
        g_h1, DEE, W2 + (size_t)e * HH * DEE, DEE, b2 + (size_t)e * HH,
        g_y2, HH, DEE, m0, s1, blockIdx.y * BN, nullptr, g_wt);
}

// out[t] = shared(t) + y2[slot0(t)] + y2[slot1(t)]
__global__ void k_combine(float* __restrict__ out) {
    const int n4 = HH / 4;
    int i = blockIdx.x * blockDim.x + threadIdx.x;
    if (i >= TT * n4) return;
    int t = i / n4;
    int c = i - t * n4;
    int s0 = g_slot[t * 2 + 0];
    int s1 = g_slot[t * 2 + 1];
    const float4* y = (const float4*)g_y2;
    float4 o = ((const float4*)out)[i];
    float4 a = y[(size_t)s0 * n4 + c];
    float4 b = y[(size_t)s1 * n4 + c];
    o.x += a.x + b.x;
    o.y += a.y + b.y;
    o.z += a.z + b.z;
    o.w += a.w + b.w;
    ((float4*)out)[i] = o;
}

// ---------------- launch (identical to passing R1) ----------------
extern "C" void kernel_launch(void* const* d_in, const int* in_sizes, int n_in,
                              void* d_out, int out_size) {
    const float* x   = (const float*)d_in[0];
    const float* Wg  = (const float*)d_in[1];
    const float* W1  = (const float*)d_in[2];
    const float* b1  = (const float*)d_in[3];
    const float* W2  = (const float*)d_in[4];
    const float* b2  = (const float*)d_in[5];
    const float* Ws1 = (const float*)d_in[6];
    const float* bs1 = (const float*)d_in[7];
    const float* Ws2 = (const float*)d_in[8];
    const float* bs2 = (const float*)d_in[9];
    float* out = (float*)d_out;

    k_zero_cnt<<<1, 32>>>();
    k_gate<<<TT / 8, 256>>>(x, Wg);
    k_prefix<<<1, 32>>>();
    k_scatter<<<TT / 256, 256>>>();

    k_shared_fc1<<<dim3(TT / BM, DSS / BN), NTH>>>(x, Ws1, bs1);
    k_shared_fc2<<<dim3(TT / BM, HH / BN),  NTH>>>(Ws2, bs2, out);

    k_routed_fc1<<<dim3(TT / BM, 1, EE),       NTH>>>(x, W1, b1);
    k_routed_fc2<<<dim3(TT / BM, HH / BN, EE), NTH>>>(W2, b2);

    k_combine<<<(TT * (HH / 4) + 255) / 256, 256>>>(out);
}

// round 9
// speedup vs baseline: 1.2358x; 1.2358x over previous
#include <cuda_runtime.h>
#include <math.h>
#include <stdint.h>

// Problem dims (fixed by the reference)
#define TT  16384   // tokens = B*S
#define HH  1024    // hidden
#define EE  8       // routed experts
#define KK  2       // top-k
#define DEE 128     // routed expert hidden
#define DSS 512     // shared expert hidden

// ---------------- device scratch ----------------
__device__ int   g_cnt[EE];
__device__ int   g_off[EE + 1];
__device__ int   g_pos[EE];
__device__ int   g_top_idx[TT * KK];
__device__ float g_top_w[TT * KK];
__device__ int   g_tok[TT * KK];
__device__ float g_wt[TT * KK];
__device__ int   g_slot[TT * KK];
__device__ float g_h1[TT * KK * DEE];
__device__ float g_hs[TT * DSS];
__device__ float g_y2[(size_t)TT * KK * HH];

// ---------------- small kernels (unchanged from passing R1/R8) ----------------
__global__ void k_zero_cnt() {
    if (threadIdx.x < EE) g_cnt[threadIdx.x] = 0;
}

__global__ void k_gate(const float* __restrict__ x, const float* __restrict__ Wg) {
    int warp = (blockIdx.x * blockDim.x + threadIdx.x) >> 5;
    int lane = threadIdx.x & 31;
    if (warp >= TT) return;
    const float* xr = x + (size_t)warp * HH;
    float acc[EE];
#pragma unroll
    for (int e = 0; e < EE; e++) acc[e] = 0.f;
    for (int j = lane; j < HH; j += 32) {
        float xv = xr[j];
#pragma unroll
        for (int e = 0; e < EE; e++) acc[e] += xv * Wg[e * HH + j];
    }
#pragma unroll
    for (int e = 0; e < EE; e++) {
#pragma unroll
        for (int off = 16; off; off >>= 1)
            acc[e] += __shfl_xor_sync(0xFFFFFFFFu, acc[e], off);
    }
    if (lane == 0) {
        float mx = acc[0];
#pragma unroll
        for (int e = 1; e < EE; e++) mx = fmaxf(mx, acc[e]);
        float p[EE], s = 0.f;
#pragma unroll
        for (int e = 0; e < EE; e++) { p[e] = expf(acc[e] - mx); s += p[e]; }
        int i0 = 0;
#pragma unroll
        for (int e = 1; e < EE; e++) if (p[e] > p[i0]) i0 = e;
        int i1 = (i0 == 0) ? 1 : 0;
#pragma unroll
        for (int e = 0; e < EE; e++) if (e != i0 && p[e] > p[i1]) i1 = e;
        float sc0 = p[i0] / s, sc1 = p[i1] / s;
        float inv = 1.f / (sc0 + sc1 + 1e-20f);
        g_top_idx[warp * 2 + 0] = i0;
        g_top_idx[warp * 2 + 1] = i1;
        g_top_w[warp * 2 + 0] = sc0 * inv;
        g_top_w[warp * 2 + 1] = sc1 * inv;
        atomicAdd(&g_cnt[i0], 1);
        atomicAdd(&g_cnt[i1], 1);
    }
}

__global__ void k_prefix() {
    if (threadIdx.x == 0) {
        int acc = 0;
#pragma unroll
        for (int e = 0; e < EE; e++) { g_off[e] = acc; acc += g_cnt[e]; }
        g_off[EE] = acc;
    }
    if (threadIdx.x < EE) g_pos[threadIdx.x] = 0;
}

__global__ void k_scatter() {
    int t = blockIdx.x * blockDim.x + threadIdx.x;
    if (t >= TT) return;
#pragma unroll
    for (int k = 0; k < KK; k++) {
        int e = g_top_idx[t * 2 + k];
        int s = g_off[e] + atomicAdd(&g_pos[e], 1);
        g_tok[s] = t;
        g_wt[s] = g_top_w[t * 2 + k];
        g_slot[t * 2 + k] = s;
    }
}

// ---------------- 3xTF32 mma GEMM, double-buffered: C[M,N] = A[M,K]*B[N,K]^T ----------------
#define BM 128
#define BN 128
#define BK 16
#define PAD 8
#define NTH 256

__device__ __forceinline__ uint32_t f2tf32(float f) {
    uint32_t r;
    asm("cvt.rna.tf32.f32 %0, %1;" : "=r"(r) : "f"(f));
    return r;
}

#define MMATF32(d, a, b) \
    asm volatile("mma.sync.aligned.m16n8k8.row.col.f32.tf32.tf32.f32 " \
                 "{%0,%1,%2,%3}, {%4,%5,%6,%7}, {%8,%9}, {%0,%1,%2,%3};" \
                 : "+f"((d)[0]), "+f"((d)[1]), "+f"((d)[2]), "+f"((d)[3]) \
                 : "r"((a)[0]), "r"((a)[1]), "r"((a)[2]), "r"((a)[3]), \
                   "r"((b)[0]), "r"((b)[1]))

template <bool GATHER, bool RELU, bool HASBIAS, bool SCALE>
__device__ __forceinline__ void gemm_tile(
    const float* __restrict__ A, int lda,
    const float* __restrict__ B, int ldb,
    const float* __restrict__ bias,
    float* __restrict__ C, int ldc,
    int Kd, int m0, int m_end, int n0,
    const int* __restrict__ gidx,
    const float* __restrict__ rowsc)
{
    __shared__ float As[2][BK][BM + PAD];
    __shared__ float Bs[2][BK][BN + PAD];
    const int tid  = threadIdx.x;
    const int lane = tid & 31;
    const int wid  = tid >> 5;
    const int wm   = wid & 1;    // m half (64 rows)
    const int wn   = wid >> 1;   // n quarter (32 cols)

    float acc[4][4][4];
#pragma unroll
    for (int i = 0; i < 4; i++)
#pragma unroll
        for (int j = 0; j < 4; j++)
#pragma unroll
            for (int q = 0; q < 4; q++) acc[i][j][q] = 0.f;

    // staging map (identical to passing R1/R8): 2 float4 of A + 2 of B per thread per chunk
    const float* aptr[2]; bool aval[2]; int arow[2], acol[2];
    const float* bptr[2]; int brow[2], bcol[2];
#pragma unroll
    for (int i = 0; i < 2; i++) {
        int li = tid * 2 + i;
        int r = li >> 2;
        int c = (li & 3) << 2;
        arow[i] = r; acol[i] = c;
        int gm = m0 + r;
        aval[i] = gm < m_end;
        int src = 0;
        if (aval[i]) src = GATHER ? gidx[gm] : gm;
        aptr[i] = A + (size_t)src * lda + c;
        brow[i] = r; bcol[i] = c;
        bptr[i] = B + (size_t)(n0 + r) * ldb + c;
    }

    const int nch = Kd / BK;
    float4 pa[2], pb[2];

    // prologue: fetch + store chunk 0 into buffer 0
#pragma unroll
    for (int i = 0; i < 2; i++) {
        pa[i] = aval[i] ? *(const float4*)(aptr[i]) : make_float4(0.f, 0.f, 0.f, 0.f);
        pb[i] = *(const float4*)(bptr[i]);
    }
#pragma unroll
    for (int i = 0; i < 2; i++) {
        As[0][acol[i] + 0][arow[i]] = pa[i].x;
        As[0][acol[i] + 1][arow[i]] = pa[i].y;
        As[0][acol[i] + 2][arow[i]] = pa[i].z;
        As[0][acol[i] + 3][arow[i]] = pa[i].w;
        Bs[0][bcol[i] + 0][brow[i]] = pb[i].x;
        Bs[0][bcol[i] + 1][brow[i]] = pb[i].y;
        Bs[0][bcol[i] + 2][brow[i]] = pb[i].z;
        Bs[0][bcol[i] + 3][brow[i]] = pb[i].w;
    }
    __syncthreads();

    for (int kc = 0; kc < nch; kc++) {
        const bool more = (kc + 1 < nch);
        // issue next chunk's global loads early (latency hidden by compute below)
        if (more) {
            const int kn = (kc + 1) * BK;
#pragma unroll
            for (int i = 0; i < 2; i++) {
                pa[i] = aval[i] ? *(const float4*)(aptr[i] + kn) : make_float4(0.f, 0.f, 0.f, 0.f);
                pb[i] = *(const float4*)(bptr[i] + kn);
            }
        }

        // ---- compute current chunk from buffer kc&1 ----
        const int cur = kc & 1;
#pragma unroll
        for (int ks = 0; ks < 2; ks++) {
            const int kk = ks * 8 + (lane & 3);
            const int r0 = wm * 64 + (lane >> 2);
            uint32_t ah[4][4], al[4][4];
#pragma unroll
            for (int mi = 0; mi < 4; mi++) {
                float f0 = As[cur][kk][r0 + mi * 16];
                float f1 = As[cur][kk][r0 + mi * 16 + 8];
                float f2 = As[cur][kk + 4][r0 + mi * 16];
                float f3 = As[cur][kk + 4][r0 + mi * 16 + 8];
                ah[mi][0] = f2tf32(f0); al[mi][0] = f2tf32(f0 - __uint_as_float(ah[mi][0]));
                ah[mi][1] = f2tf32(f1); al[mi][1] = f2tf32(f1 - __uint_as_float(ah[mi][1]));
                ah[mi][2] = f2tf32(f2); al[mi][2] = f2tf32(f2 - __uint_as_float(ah[mi][2]));
                ah[mi][3] = f2tf32(f3); al[mi][3] = f2tf32(f3 - __uint_as_float(ah[mi][3]));
            }
            const int c0 = wn * 32 + (lane >> 2);
            uint32_t bh[4][2], bl[4][2];
#pragma unroll
            for (int nj = 0; nj < 4; nj++) {
                float f0 = Bs[cur][kk][c0 + nj * 8];
                float f1 = Bs[cur][kk + 4][c0 + nj * 8];
                bh[nj][0] = f2tf32(f0); bl[nj][0] = f2tf32(f0 - __uint_as_float(bh[nj][0]));
                bh[nj][1] = f2tf32(f1); bl[nj][1] = f2tf32(f1 - __uint_as_float(bh[nj][1]));
            }
#pragma unroll
            for (int mi = 0; mi < 4; mi++)
#pragma unroll
                for (int nj = 0; nj < 4; nj++) {
                    MMATF32(acc[mi][nj], ah[mi], bh[nj]);
                    MMATF32(acc[mi][nj], ah[mi], bl[nj]);
                    MMATF32(acc[mi][nj], al[mi], bh[nj]);
                }
        }

        // ---- store prefetched chunk into the other buffer ----
        if (more) {
            const int nxt = (kc + 1) & 1;
#pragma unroll
            for (int i = 0; i < 2; i++) {
                As[nxt][acol[i] + 0][arow[i]] = pa[i].x;
                As[nxt][acol[i] + 1][arow[i]] = pa[i].y;
                As[nxt][acol[i] + 2][arow[i]] = pa[i].z;
                As[nxt][acol[i] + 3][arow[i]] = pa[i].w;
                Bs[nxt][bcol[i] + 0][brow[i]] = pb[i].x;
                Bs[nxt][bcol[i] + 1][brow[i]] = pb[i].y;
                Bs[nxt][bcol[i] + 2][brow[i]] = pb[i].z;
                Bs[nxt][bcol[i] + 3][brow[i]] = pb[i].w;
            }
        }
        __syncthreads();
    }

    // ---- epilogue: (+bias) (*rowscale) (relu) -> C ----
#pragma unroll
    for (int mi = 0; mi < 4; mi++) {
#pragma unroll
        for (int half = 0; half < 2; half++) {
            int gm = m0 + wm * 64 + mi * 16 + (lane >> 2) + half * 8;
            if (gm >= m_end) continue;
            float sc = SCALE ? rowsc[gm] : 1.f;
#pragma unroll
            for (int nj = 0; nj < 4; nj++) {
                int col = n0 + wn * 32 + nj * 8 + (lane & 3) * 2;
                float v0 = acc[mi][nj][half * 2 + 0];
                float v1 = acc[mi][nj][half * 2 + 1];
                if (HASBIAS) { v0 += bias[col]; v1 += bias[col + 1]; }
                if (SCALE)   { v0 *= sc; v1 *= sc; }
                if (RELU)    { v0 = fmaxf(v0, 0.f); v1 = fmaxf(v1, 0.f); }
                *(float2*)(C + (size_t)gm * ldc + col) = make_float2(v0, v1);
            }
        }
    }
}

// ---------------- GEMM wrappers (same shapes/grids as passing R8) ----------------
__global__ __launch_bounds__(NTH) void k_shared_fc1(
    const float* __restrict__ x, const float* __restrict__ Ws1,
    const float* __restrict__ bs1)
{
    gemm_tile<false, true, true, false>(
        x, HH, Ws1, HH, bs1, g_hs, DSS, HH,
        blockIdx.x * BM, TT, blockIdx.y * BN, nullptr, nullptr);
}

__global__ __launch_bounds__(NTH) void k_shared_fc2(
    const float* __restrict__ Ws2, const float* __restrict__ bs2,
    float* __restrict__ out)
{
    gemm_tile<false, false, true, false>(
        g_hs, DSS, Ws2, DSS, bs2, out, HH, DSS,
        blockIdx.x * BM, TT, blockIdx.y * BN, nullptr, nullptr);
}

__global__ __launch_bounds__(NTH) void k_routed_fc1(
    const float* __restrict__ x, const float* __restrict__ W1,
    const float* __restrict__ b1)
{
    int e = blockIdx.z;
    int s0 = g_off[e], s1 = g_off[e + 1];
    int m0 = s0 + blockIdx.x * BM;
    if (m0 >= s1) return;
    gemm_tile<true, true, true, false>(
        x, HH, W1 + (size_t)e * DEE * HH, HH, b1 + e * DEE,
        g_h1, DEE, HH, m0, s1, 0, g_tok, nullptr);
}

__global__ __launch_bounds__(NTH) void k_routed_fc2(
    const float* __restrict__ W2, const float* __restrict__ b2)
{
    int e = blockIdx.z;
    int s0 = g_off[e], s1 = g_off[e + 1];
    int m0 = s0 + blockIdx.x * BM;
    if (m0 >= s1) return;
    gemm_tile<false, false, true, true>(
        g_h1, DEE, W2 + (size_t)e * HH * DEE, DEE, b2 + (size_t)e * HH,
        g_y2, HH, DEE, m0, s1, blockIdx.y * BN, nullptr, g_wt);
}

// out[t] = shared(t) + y2[slot0(t)] + y2[slot1(t)]
__global__ void k_combine(float* __restrict__ out) {
    const int n4 = HH / 4;
    int i = blockIdx.x * blockDim.x + threadIdx.x;
    if (i >= TT * n4) return;
    int t = i / n4;
    int c = i - t * n4;
    int s0 = g_slot[t * 2 + 0];
    int s1 = g_slot[t * 2 + 1];
    const float4* y = (const float4*)g_y2;
    float4 o = ((const float4*)out)[i];
    float4 a = y[(size_t)s0 * n4 + c];
    float4 b = y[(size_t)s1 * n4 + c];
    o.x += a.x + b.x;
    o.y += a.y + b.y;
    o.z += a.z + b.z;
    o.w += a.w + b.w;
    ((float4*)out)[i] = o;
}

// ---------------- launch (identical to passing R8) ----------------
extern "C" void kernel_launch(void* const* d_in, const int* in_sizes, int n_in,
                              void* d_out, int out_size) {
    const float* x   = (const float*)d_in[0];
    const float* Wg  = (const float*)d_in[1];
    const float* W1  = (const float*)d_in[2];
    const float* b1  = (const float*)d_in[3];
    const float* W2  = (const float*)d_in[4];
    const float* b2  = (const float*)d_in[5];
    const float* Ws1 = (const float*)d_in[6];
    const float* bs1 = (const float*)d_in[7];
    const float* Ws2 = (const float*)d_in[8];
    const float* bs2 = (const float*)d_in[9];
    float* out = (float*)d_out;

    k_zero_cnt<<<1, 32>>>();
    k_gate<<<TT / 8, 256>>>(x, Wg);
    k_prefix<<<1, 32>>>();
    k_scatter<<<TT / 256, 256>>>();

    k_shared_fc1<<<dim3(TT / BM, DSS / BN), NTH>>>(x, Ws1, bs1);
    k_shared_fc2<<<dim3(TT / BM, HH / BN),  NTH>>>(Ws2, bs2, out);

    k_routed_fc1<<<dim3(TT / BM, 1, EE),       NTH>>>(x, W1, b1);
    k_routed_fc2<<<dim3(TT / BM, HH / BN, EE), NTH>>>(W2, b2);

    k_combine<<<(TT * (HH / 4) + 255) / 256, 256>>>(out);
}

// round 14
// speedup vs baseline: 1.6558x; 1.3399x over previous
#include <cuda_runtime.h>
#include <cuda_bf16.h>
#include <math.h>
#include <stdint.h>

// Problem dims (fixed by the reference)
#define TT  16384   // tokens = B*S
#define HH  1024    // hidden
#define EE  8       // routed experts
#define KK  2       // top-k
#define DEE 128     // routed expert hidden
#define DSS 512     // shared expert hidden

// ---------------- device scratch ----------------
__device__ int   g_cnt[EE];
__device__ int   g_off[EE + 1];
__device__ int   g_pos[EE];
__device__ int   g_top_idx[TT * KK];
__device__ float g_top_w[TT * KK];
__device__ int   g_tok[TT * KK];
__device__ float g_wt[TT * KK];
__device__ int   g_slot[TT * KK];
__device__ float g_h1[TT * KK * DEE];
__device__ float g_hs[TT * DSS];
__device__ float g_y2[(size_t)TT * KK * HH];

// ---------------- small kernels (unchanged from passing R1/R9) ----------------
__global__ void k_zero_cnt() {
    if (threadIdx.x < EE) g_cnt[threadIdx.x] = 0;
}

__global__ void k_gate(const float* __restrict__ x, const float* __restrict__ Wg) {
    int warp = (blockIdx.x * blockDim.x + threadIdx.x) >> 5;
    int lane = threadIdx.x & 31;
    if (warp >= TT) return;
    const float* xr = x + (size_t)warp * HH;
    float acc[EE];
#pragma unroll
    for (int e = 0; e < EE; e++) acc[e] = 0.f;
    for (int j = lane; j < HH; j += 32) {
        float xv = xr[j];
#pragma unroll
        for (int e = 0; e < EE; e++) acc[e] += xv * Wg[e * HH + j];
    }
#pragma unroll
    for (int e = 0; e < EE; e++) {
#pragma unroll
        for (int off = 16; off; off >>= 1)
            acc[e] += __shfl_xor_sync(0xFFFFFFFFu, acc[e], off);
    }
    if (lane == 0) {
        float mx = acc[0];
#pragma unroll
        for (int e = 1; e < EE; e++) mx = fmaxf(mx, acc[e]);
        float p[EE], s = 0.f;
#pragma unroll
        for (int e = 0; e < EE; e++) { p[e] = expf(acc[e] - mx); s += p[e]; }
        int i0 = 0;
#pragma unroll
        for (int e = 1; e < EE; e++) if (p[e] > p[i0]) i0 = e;
        int i1 = (i0 == 0) ? 1 : 0;
#pragma unroll
        for (int e = 0; e < EE; e++) if (e != i0 && p[e] > p[i1]) i1 = e;
        float sc0 = p[i0] / s, sc1 = p[i1] / s;
        float inv = 1.f / (sc0 + sc1 + 1e-20f);
        g_top_idx[warp * 2 + 0] = i0;
        g_top_idx[warp * 2 + 1] = i1;
        g_top_w[warp * 2 + 0] = sc0 * inv;
        g_top_w[warp * 2 + 1] = sc1 * inv;
        atomicAdd(&g_cnt[i0], 1);
        atomicAdd(&g_cnt[i1], 1);
    }
}

__global__ void k_prefix() {
    if (threadIdx.x == 0) {
        int acc = 0;
#pragma unroll
        for (int e = 0; e < EE; e++) { g_off[e] = acc; acc += g_cnt[e]; }
        g_off[EE] = acc;
    }
    if (threadIdx.x < EE) g_pos[threadIdx.x] = 0;
}

__global__ void k_scatter() {
    int t = blockIdx.x * blockDim.x + threadIdx.x;
    if (t >= TT) return;
#pragma unroll
    for (int k = 0; k < KK; k++) {
        int e = g_top_idx[t * 2 + k];
        int s = g_off[e] + atomicAdd(&g_pos[e], 1);
        g_tok[s] = t;
        g_wt[s] = g_top_w[t * 2 + k];
        g_slot[t * 2 + k] = s;
    }
}

// ---------------- bf16 hi/lo 3-pass mma GEMM, double-buffered ----------------
// C[M,N] = A[M,K]*B[N,K]^T.  Split fp32 -> bf16 hi + bf16 lo at STAGING time.
#define BM 128
#define BN 128
#define BK 16
#define NTH 256
#define APITCH 24   // bf16 units per A row (16 + 8 pad) -> conflict-free frag LDS
#define BPITCH 20   // bf16 units per B row (16 + 4 pad)

// pack two floats into bf16x2: f0 -> low half, f1 -> high half
__device__ __forceinline__ uint32_t pack_bf2(float f0, float f1) {
    uint32_t r;
    asm("cvt.rn.bf16x2.f32 %0, %1, %2;" : "=r"(r) : "f"(f1), "f"(f0));
    return r;
}
// hi/lo split of a float pair
__device__ __forceinline__ void split2(float f0, float f1, uint32_t& hp, uint32_t& lp) {
    hp = pack_bf2(f0, f1);
    float h0 = __uint_as_float(hp << 16);
    float h1 = __uint_as_float(hp & 0xFFFF0000u);
    lp = pack_bf2(f0 - h0, f1 - h1);
}

#define MMABF16(d, a, b) \
    asm volatile("mma.sync.aligned.m16n8k16.row.col.f32.bf16.bf16.f32 " \
                 "{%0,%1,%2,%3}, {%4,%5,%6,%7}, {%8,%9}, {%0,%1,%2,%3};" \
                 : "+f"((d)[0]), "+f"((d)[1]), "+f"((d)[2]), "+f"((d)[3]) \
                 : "r"((a)[0]), "r"((a)[1]), "r"((a)[2]), "r"((a)[3]), \
                   "r"((b)[0]), "r"((b)[1]))

template <bool GATHER, bool RELU, bool HASBIAS, bool SCALE>
__device__ __forceinline__ void gemm_tile(
    const float* __restrict__ A, int lda,
    const float* __restrict__ B, int ldb,
    const float* __restrict__ bias,
    float* __restrict__ C, int ldc,
    int Kd, int m0, int m_end, int n0,
    const int* __restrict__ gidx,
    const float* __restrict__ rowsc)
{
    // split hi/lo bf16 tiles, double-buffered: 2*(128*24 + 128*24 + 128*20 + 128*20)*2B = 45056 B
    __shared__ uint16_t Ash[2][BM][APITCH];
    __shared__ uint16_t Asl[2][BM][APITCH];
    __shared__ uint16_t Bsh[2][BN][BPITCH];
    __shared__ uint16_t Bsl[2][BN][BPITCH];

    const int tid  = threadIdx.x;
    const int lane = tid & 31;
    const int wid  = tid >> 5;
    const int wm   = wid & 1;    // m half (64 rows)
    const int wn   = wid >> 1;   // n quarter (32 cols)

    float acc[4][4][4];
#pragma unroll
    for (int i = 0; i < 4; i++)
#pragma unroll
        for (int j = 0; j < 4; j++)
#pragma unroll
            for (int q = 0; q < 4; q++) acc[i][j][q] = 0.f;

    // staging map (identical addressing to passing R9): 2 float4 of A + 2 of B per thread per chunk
    const float* aptr[2]; bool aval[2]; int arow[2], acol[2];
    const float* bptr[2]; int brow[2], bcol[2];
#pragma unroll
    for (int i = 0; i < 2; i++) {
        int li = tid * 2 + i;
        int r = li >> 2;
        int c = (li & 3) << 2;      // bf16/float column index (4 elements)
        arow[i] = r; acol[i] = c;
        int gm = m0 + r;
        aval[i] = gm < m_end;
        int src = 0;
        if (aval[i]) src = GATHER ? gidx[gm] : gm;
        aptr[i] = A + (size_t)src * lda + c;
        brow[i] = r; bcol[i] = c;
        bptr[i] = B + (size_t)(n0 + r) * ldb + c;
    }

    const int nch = Kd / BK;
    float4 pa[2], pb[2];

    // prologue: fetch chunk 0, split, store into buffer 0
#pragma unroll
    for (int i = 0; i < 2; i++) {
        pa[i] = aval[i] ? *(const float4*)(aptr[i]) : make_float4(0.f, 0.f, 0.f, 0.f);
        pb[i] = *(const float4*)(bptr[i]);
    }
#pragma unroll
    for (int i = 0; i < 2; i++) {
        uint32_t h0, l0, h1, l1;
        split2(pa[i].x, pa[i].y, h0, l0);
        split2(pa[i].z, pa[i].w, h1, l1);
        *(uint2*)&Ash[0][arow[i]][acol[i]] = make_uint2(h0, h1);
        *(uint2*)&Asl[0][arow[i]][acol[i]] = make_uint2(l0, l1);
        split2(pb[i].x, pb[i].y, h0, l0);
        split2(pb[i].z, pb[i].w, h1, l1);
        *(uint2*)&Bsh[0][brow[i]][bcol[i]] = make_uint2(h0, h1);
        *(uint2*)&Bsl[0][brow[i]][bcol[i]] = make_uint2(l0, l1);
    }
    __syncthreads();

    for (int kc = 0; kc < nch; kc++) {
        const bool more = (kc + 1 < nch);
        if (more) {
            const int kn = (kc + 1) * BK;
#pragma unroll
            for (int i = 0; i < 2; i++) {
                pa[i] = aval[i] ? *(const float4*)(aptr[i] + kn) : make_float4(0.f, 0.f, 0.f, 0.f);
                pb[i] = *(const float4*)(bptr[i] + kn);
            }
        }

        // ---- fragments straight from split smem (no in-loop cvt) ----
        const int cur = kc & 1;
        const int c2  = (lane & 3) * 2;           // bf16 k index of pair start
        uint32_t ah[4][4], al[4][4], bh[4][2], bl[4][2];
#pragma unroll
        for (int mi = 0; mi < 4; mi++) {
            const int r = wm * 64 + mi * 16 + (lane >> 2);
            ah[mi][0] = *(const uint32_t*)&Ash[cur][r][c2];
            ah[mi][1] = *(const uint32_t*)&Ash[cur][r + 8][c2];
            ah[mi][2] = *(const uint32_t*)&Ash[cur][r][c2 + 8];
            ah[mi][3] = *(const uint32_t*)&Ash[cur][r + 8][c2 + 8];
            al[mi][0] = *(const uint32_t*)&Asl[cur][r][c2];
            al[mi][1] = *(const uint32_t*)&Asl[cur][r + 8][c2];
            al[mi][2] = *(const uint32_t*)&Asl[cur][r][c2 + 8];
            al[mi][3] = *(const uint32_t*)&Asl[cur][r + 8][c2 + 8];
        }
#pragma unroll
        for (int nj = 0; nj < 4; nj++) {
            const int n = wn * 32 + nj * 8 + (lane >> 2);
            bh[nj][0] = *(const uint32_t*)&Bsh[cur][n][c2];
            bh[nj][1] = *(const uint32_t*)&Bsh[cur][n][c2 + 8];
            bl[nj][0] = *(const uint32_t*)&Bsl[cur][n][c2];
            bl[nj][1] = *(const uint32_t*)&Bsl[cur][n][c2 + 8];
        }
        // 3 passes: Ah*Bh + Ah*Bl + Al*Bh  (48 MMAs)
#pragma unroll
        for (int mi = 0; mi < 4; mi++)
#pragma unroll
            for (int nj = 0; nj < 4; nj++) {
                MMABF16(acc[mi][nj], ah[mi], bh[nj]);
                MMABF16(acc[mi][nj], ah[mi], bl[nj]);
                MMABF16(acc[mi][nj], al[mi], bh[nj]);
            }

        // ---- split + store prefetched chunk into other buffer ----
        if (more) {
            const int nxt = (kc + 1) & 1;
#pragma unroll
            for (int i = 0; i < 2; i++) {
                uint32_t h0, l0, h1, l1;
                split2(pa[i].x, pa[i].y, h0, l0);
                split2(pa[i].z, pa[i].w, h1, l1);
                *(uint2*)&Ash[nxt][arow[i]][acol[i]] = make_uint2(h0, h1);
                *(uint2*)&Asl[nxt][arow[i]][acol[i]] = make_uint2(l0, l1);
                split2(pb[i].x, pb[i].y, h0, l0);
                split2(pb[i].z, pb[i].w, h1, l1);
                *(uint2*)&Bsh[nxt][brow[i]][bcol[i]] = make_uint2(h0, h1);
                *(uint2*)&Bsl[nxt][brow[i]][bcol[i]] = make_uint2(l0, l1);
            }
        }
        __syncthreads();
    }

    // ---- epilogue: (+bias) (*rowscale) (relu) -> C (same acc layout as R9) ----
#pragma unroll
    for (int mi = 0; mi < 4; mi++) {
#pragma unroll
        for (int half = 0; half < 2; half++) {
            int gm = m0 + wm * 64 + mi * 16 + (lane >> 2) + half * 8;
            if (gm >= m_end) continue;
            float sc = SCALE ? rowsc[gm] : 1.f;
#pragma unroll
            for (int nj = 0; nj < 4; nj++) {
                int col = n0 + wn * 32 + nj * 8 + (lane & 3) * 2;
                float v0 = acc[mi][nj][half * 2 + 0];
                float v1 = acc[mi][nj][half * 2 + 1];
                if (HASBIAS) { v0 += bias[col]; v1 += bias[col + 1]; }
                if (SCALE)   { v0 *= sc; v1 *= sc; }
                if (RELU)    { v0 = fmaxf(v0, 0.f); v1 = fmaxf(v1, 0.f); }
                *(float2*)(C + (size_t)gm * ldc + col) = make_float2(v0, v1);
            }
        }
    }
}

// ---------------- GEMM wrappers (same shapes/grids as passing R9) ----------------
__global__ __launch_bounds__(NTH) void k_shared_fc1(
    const float* __restrict__ x, const float* __restrict__ Ws1,
    const float* __restrict__ bs1)
{
    gemm_tile<false, true, true, false>(
        x, HH, Ws1, HH, bs1, g_hs, DSS, HH,
        blockIdx.x * BM, TT, blockIdx.y * BN, nullptr, nullptr);
}

__global__ __launch_bounds__(NTH) void k_shared_fc2(
    const float* __restrict__ Ws2, const float* __restrict__ bs2,
    float* __restrict__ out)
{
    gemm_tile<false, false, true, false>(
        g_hs, DSS, Ws2, DSS, bs2, out, HH, DSS,
        blockIdx.x * BM, TT, blockIdx.y * BN, nullptr, nullptr);
}

__global__ __launch_bounds__(NTH) void k_routed_fc1(
    const float* __restrict__ x, const float* __restrict__ W1,
    const float* __restrict__ b1)
{
    int e = blockIdx.z;
    int s0 = g_off[e], s1 = g_off[e + 1];
    int m0 = s0 + blockIdx.x * BM;
    if (m0 >= s1) return;
    gemm_tile<true, true, true, false>(
        x, HH, W1 + (size_t)e * DEE * HH, HH, b1 + e * DEE,
        g_h1, DEE, HH, m0, s1, 0, g_tok, nullptr);
}

__global__ __launch_bounds__(NTH) void k_routed_fc2(
    const float* __restrict__ W2, const float* __restrict__ b2)
{
    int e = blockIdx.z;
    int s0 = g_off[e], s1 = g_off[e + 1];
    int m0 = s0 + blockIdx.x * BM;
    if (m0 >= s1) return;
    gemm_tile<false, false, true, true>(
        g_h1, DEE, W2 + (size_t)e * HH * DEE, DEE, b2 + (size_t)e * HH,
        g_y2, HH, DEE, m0, s1, blockIdx.y * BN, nullptr, g_wt);
}

// out[t] = shared(t) + y2[slot0(t)] + y2[slot1(t)]
__global__ void k_combine(float* __restrict__ out) {
    const int n4 = HH / 4;
    int i = blockIdx.x * blockDim.x + threadIdx.x;
    if (i >= TT * n4) return;
    int t = i / n4;
    int c = i - t * n4;
    int s0 = g_slot[t * 2 + 0];
    int s1 = g_slot[t * 2 + 1];
    const float4* y = (const float4*)g_y2;
    float4 o = ((const float4*)out)[i];
    float4 a = y[(size_t)s0 * n4 + c];
    float4 b = y[(size_t)s1 * n4 + c];
    o.x += a.x + b.x;
    o.y += a.y + b.y;
    o.z += a.z + b.z;
    o.w += a.w + b.w;
    ((float4*)out)[i] = o;
}

// ---------------- launch (identical to passing R9) ----------------
extern "C" void kernel_launch(void* const* d_in, const int* in_sizes, int n_in,
                              void* d_out, int out_size) {
    const float* x   = (const float*)d_in[0];
    const float* Wg  = (const float*)d_in[1];
    const float* W1  = (const float*)d_in[2];
    const float* b1  = (const float*)d_in[3];
    const float* W2  = (const float*)d_in[4];
    const float* b2  = (const float*)d_in[5];
    const float* Ws1 = (const float*)d_in[6];
    const float* bs1 = (const float*)d_in[7];
    const float* Ws2 = (const float*)d_in[8];
    const float* bs2 = (const float*)d_in[9];
    float* out = (float*)d_out;

    k_zero_cnt<<<1, 32>>>();
    k_gate<<<TT / 8, 256>>>(x, Wg);
    k_prefix<<<1, 32>>>();
    k_scatter<<<TT / 256, 256>>>();

    k_shared_fc1<<<dim3(TT / BM, DSS / BN), NTH>>>(x, Ws1, bs1);
    k_shared_fc2<<<dim3(TT / BM, HH / BN),  NTH>>>(Ws2, bs2, out);

    k_routed_fc1<<<dim3(TT / BM, 1, EE),       NTH>>>(x, W1, b1);
    k_routed_fc2<<<dim3(TT / BM, HH / BN, EE), NTH>>>(W2, b2);

    k_combine<<<(TT * (HH / 4) + 255) / 256, 256>>>(out);
}